// round 4
// baseline (speedup 1.0000x reference)
#include <cuda_runtime.h>

// HopfieldNetwork_58823872086839 — output is identically 1.0f.
// (threshold=0, W ∈ [0,8] forever via the STDP clip, binary states ⇒
//  pot = s·W[idx] ≥ 0 ⇒ every neuron fires at t0=0 in every sweep ⇒ the
//  returned states tensor is all-ones regardless of input/perm/STDP.)
//
// R4: kernel time is pinned at a launch/dispatch floor (3.58–3.81 µs across
// three radically different bodies). Remaining lever: halve the CTA count by
// using sm_103a 256-bit stores (st.global.v8.f32 -> STG.E.256).
// 196 CTAs x 256 threads x one 32B store = 1,605,632 bytes exactly.

__global__ void __launch_bounds__(256, 1)
hopfield_ones_256(float* __restrict__ out, unsigned n8) {
    unsigned i = blockIdx.x * 256u + threadIdx.x;
    if (i < n8) {
        float* p = out + (size_t)i * 8u;
        asm volatile(
            "st.global.v8.f32 [%0], {%1,%1,%1,%1,%1,%1,%1,%1};"
            :: "l"(p), "f"(1.0f) : "memory");
    }
}

__global__ void hopfield_ones_tail(float* __restrict__ out,
                                   unsigned start, unsigned n) {
    unsigned i = start + threadIdx.x;
    if (i < n) out[i] = 1.0f;
}

extern "C" void kernel_launch(void* const* d_in, const int* in_sizes, int n_in,
                              void* d_out, int out_size) {
    (void)d_in; (void)in_sizes; (void)n_in;

    unsigned n = (unsigned)out_size;   // 401408 floats = 1,605,632 bytes
    unsigned n8 = n / 8u;              // 50176 x 32B stores = 196 * 256 exactly
    if (n8) {
        unsigned blocks = (n8 + 255u) / 256u;   // 196
        hopfield_ones_256<<<blocks, 256>>>((float*)d_out, n8);
    }
    unsigned tail_start = n8 * 8u;
    if (tail_start < n) {              // not taken for this problem's shape
        hopfield_ones_tail<<<1, 256>>>((float*)d_out, tail_start, n);
    }
}

// round 5
// speedup vs baseline: 1.0854x; 1.0854x over previous
#include <cuda_runtime.h>

// HopfieldNetwork_58823872086839 — output is identically 1.0f.
// (threshold=0, W ∈ [0,8] forever via the STDP clip, binary states ⇒
//  pot = s·W[idx] ≥ 0 ⇒ every neuron fires at t0=0 in every sweep ⇒ the
//  returned states tensor is all-ones regardless of input/perm/STDP.)
//
// R5: R4 (STG.256, 196 CTAs) regressed — 256-bit stores double L1tex
// wavefronts per instruction (8 lines/warp vs 4) and lengthen the drain
// tail. This round isolates the CTA-count variable: keep one predicated
// STG.128 per thread (R3's known-good shape) but use 512-thread blocks
// -> 196 CTAs, identical store stream to R3.

__global__ void __launch_bounds__(512, 1)
hopfield_ones(float4* __restrict__ out4, unsigned n4) {
    unsigned i = blockIdx.x * 512u + threadIdx.x;
    if (i < n4) {
        out4[i] = make_float4(1.0f, 1.0f, 1.0f, 1.0f);
    }
}

__global__ void hopfield_ones_tail(float* __restrict__ out,
                                   unsigned start, unsigned n) {
    unsigned i = start + threadIdx.x;
    if (i < n) out[i] = 1.0f;
}

extern "C" void kernel_launch(void* const* d_in, const int* in_sizes, int n_in,
                              void* d_out, int out_size) {
    (void)d_in; (void)in_sizes; (void)n_in;

    unsigned n = (unsigned)out_size;   // 401408 floats
    unsigned n4 = n / 4u;              // 100352 float4 = 196 * 512 exactly
    if (n4) {
        unsigned blocks = (n4 + 511u) / 512u;   // 196
        hopfield_ones<<<blocks, 512>>>((float4*)d_out, n4);
    }
    unsigned tail_start = n4 * 4u;
    if (tail_start < n) {              // not taken for this problem's shape
        hopfield_ones_tail<<<1, 256>>>((float*)d_out, tail_start, n);
    }
}

// round 6
// speedup vs baseline: 1.5105x; 1.3916x over previous
#include <cuda_runtime.h>

// HopfieldNetwork_58823872086839 — output is identically 1.0f.
// (threshold=0, W ∈ [0,8] forever via the STDP clip, binary states ⇒
//  pot = s·W[idx] ≥ 0 ⇒ every neuron fires at t0=0 in every sweep ⇒ the
//  returned states tensor is all-ones regardless of input/perm/STDP.)
//
// R6: replay-level timing shows grid granularity is the lever:
//   392 CTAs (R1/R2/R3): dur 4.54-4.61 us   (kernel-vs-dur gap ~0.9 us)
//   196 CTAs (R4/R5):    dur 6.37-6.91 us   (gap ~2.6 us) — regardless of
//   store width. Finer CTAs interleave into the sequential dispatch ramp and
//   retire/drain earlier. Push one step finer: 784 CTAs x 128 threads, one
//   predicated STG.128 per thread (identical store stream to R3).

__global__ void __launch_bounds__(128, 1)
hopfield_ones(float4* __restrict__ out4, unsigned n4) {
    unsigned i = blockIdx.x * 128u + threadIdx.x;
    if (i < n4) {
        out4[i] = make_float4(1.0f, 1.0f, 1.0f, 1.0f);
    }
}

__global__ void hopfield_ones_tail(float* __restrict__ out,
                                   unsigned start, unsigned n) {
    unsigned i = start + threadIdx.x;
    if (i < n) out[i] = 1.0f;
}

extern "C" void kernel_launch(void* const* d_in, const int* in_sizes, int n_in,
                              void* d_out, int out_size) {
    (void)d_in; (void)in_sizes; (void)n_in;

    unsigned n = (unsigned)out_size;   // 401408 floats
    unsigned n4 = n / 4u;              // 100352 float4 = 784 * 128 exactly
    if (n4) {
        unsigned blocks = (n4 + 127u) / 128u;   // 784
        hopfield_ones<<<blocks, 128>>>((float4*)d_out, n4);
    }
    unsigned tail_start = n4 * 4u;
    if (tail_start < n) {              // not taken for this problem's shape
        hopfield_ones_tail<<<1, 128>>>((float*)d_out, tail_start, n);
    }
}